// round 2
// baseline (speedup 1.0000x reference)
#include <cuda_runtime.h>
#include <math.h>
#include <stddef.h>

// Problem constants
#define HH   2048
#define NHH  16
#define DHH  128
#define FFF  8192
#define BB   2
#define SS   2048
#define MT   (BB*SS)      // 4096 total rows
#define QLD  (3*HH)       // 6144, qkv row stride
#define LN_EPS 1e-5f
#define ATTN_SCALE 0.088388347648318447f  // 1/sqrt(128)

// ---------------- scratch (static device globals; no allocation) -------------
__device__ float g_h[(size_t)MT * HH];            // LN output          32 MB
__device__ float g_qkv[(size_t)MT * QLD];         // QKV                96 MB
__device__ float g_scores[(size_t)BB * NHH * SS * SS]; // attn scores  512 MB
__device__ float g_ctx[(size_t)MT * HH];          // attention context  32 MB
__device__ float g_x1[(size_t)MT * HH];           // x + attn_out       32 MB
__device__ float g_inter[(size_t)MT * FFF];       // MLP intermediate  128 MB

// ---------------- reductions -------------------------------------------------
__device__ __forceinline__ float warpReduceSum(float v) {
#pragma unroll
    for (int o = 16; o > 0; o >>= 1) v += __shfl_xor_sync(0xffffffffu, v, o);
    return v;
}
__device__ __forceinline__ float warpReduceMax(float v) {
#pragma unroll
    for (int o = 16; o > 0; o >>= 1) v = fmaxf(v, __shfl_xor_sync(0xffffffffu, v, o));
    return v;
}

// ---------------- LayerNorm: one block (256 thr) per row of 2048 -------------
__device__ __forceinline__ void layernorm_row(const float* __restrict__ in,
                                              const float* __restrict__ g,
                                              const float* __restrict__ be,
                                              float* __restrict__ out) {
    const int row = blockIdx.x, tid = threadIdx.x;
    const float* xr = in + (size_t)row * HH;
    float v[8];
    float s = 0.f;
#pragma unroll
    for (int i = 0; i < 8; i++) { v[i] = xr[tid + i * 256]; s += v[i]; }

    __shared__ float sh[8];
    __shared__ float s_mu, s_rs;
    float ws = warpReduceSum(s);
    if ((tid & 31) == 0) sh[tid >> 5] = ws;
    __syncthreads();
    if (tid == 0) {
        float t = 0.f;
#pragma unroll
        for (int i = 0; i < 8; i++) t += sh[i];
        s_mu = t * (1.0f / HH);
    }
    __syncthreads();
    const float mu = s_mu;
    float var = 0.f;
#pragma unroll
    for (int i = 0; i < 8; i++) { float d = v[i] - mu; var += d * d; }
    float wv = warpReduceSum(var);
    if ((tid & 31) == 0) sh[tid >> 5] = wv;
    __syncthreads();
    if (tid == 0) {
        float t = 0.f;
#pragma unroll
        for (int i = 0; i < 8; i++) t += sh[i];
        s_rs = rsqrtf(t * (1.0f / HH) + LN_EPS);
    }
    __syncthreads();
    const float rs = s_rs;
    float* orow = out + (size_t)row * HH;
#pragma unroll
    for (int i = 0; i < 8; i++) {
        int c = tid + i * 256;
        orow[c] = (v[i] - mu) * rs * g[c] + be[c];
    }
}

// ---------------- 128x128x8 SGEMM tile, 256 thr, 8x8/thr, double-buffered ----
// BT=false: C = A[M,K] @ B[K,N]   (row-major, leading dims lda/ldb/ldc)
// BT=true : C = A[M,K] @ B[N,K]^T (both K-contiguous; used for Q*K^T)
template <bool BT, class Epi>
__device__ __forceinline__ void gemm_tile(const float* __restrict__ A,
                                          const float* __restrict__ Bm,
                                          float* __restrict__ C,
                                          int K, int lda, int ldb, int ldc,
                                          Epi epi) {
    __shared__ float As[2][8][128];   // k-major
    __shared__ float Bs[2][8][128];   // k-major
    const int tid = threadIdx.x;
    const int m0 = blockIdx.y * 128, n0 = blockIdx.x * 128;
    const int tx = tid & 15, ty = tid >> 4;

    float acc[8][8];
#pragma unroll
    for (int i = 0; i < 8; i++)
#pragma unroll
        for (int j = 0; j < 8; j++) acc[i][j] = 0.f;

    const int ar = tid >> 1, ac = (tid & 1) * 4;   // A: 128 rows x 8 cols, float4
    const int br = tid >> 5, bc = (tid & 31) * 4;  // B (BT=false): 8 rows x 128 cols

    const float* Aptr = A + (size_t)(m0 + ar) * lda + ac;
    const float* Bptr = BT ? (Bm + (size_t)(n0 + ar) * ldb + ac)
                           : (Bm + (size_t)br * ldb + n0 + bc);

    // ---- preload tile 0 into buffer 0 ----
    {
        float4 av = *reinterpret_cast<const float4*>(Aptr);
        As[0][ac + 0][ar] = av.x; As[0][ac + 1][ar] = av.y;
        As[0][ac + 2][ar] = av.z; As[0][ac + 3][ar] = av.w;
        float4 bv = *reinterpret_cast<const float4*>(Bptr);
        if (BT) {
            Bs[0][ac + 0][ar] = bv.x; Bs[0][ac + 1][ar] = bv.y;
            Bs[0][ac + 2][ar] = bv.z; Bs[0][ac + 3][ar] = bv.w;
        } else {
            *reinterpret_cast<float4*>(&Bs[0][br][bc]) = bv;
        }
    }
    __syncthreads();

    int buf = 0;
    for (int k0 = 0; k0 < K; k0 += 8) {
        const bool has_next = (k0 + 8) < K;
        float4 av_n, bv_n;
        if (has_next) {
            // A next: advance 8 along K
            av_n = *reinterpret_cast<const float4*>(Aptr + (k0 + 8));
            bv_n = *reinterpret_cast<const float4*>(
                BT ? (Bptr + (k0 + 8)) : (Bptr + (size_t)(k0 + 8) * ldb));
        }
        // ---- compute from smem[buf] (hides the gmem loads above) ----
#pragma unroll
        for (int k = 0; k < 8; k++) {
            float a[8], b[8];
#pragma unroll
            for (int i = 0; i < 8; i++) a[i] = As[buf][k][ty * 8 + i];
#pragma unroll
            for (int j = 0; j < 8; j++) b[j] = Bs[buf][k][tx * 8 + j];
#pragma unroll
            for (int i = 0; i < 8; i++)
#pragma unroll
                for (int j = 0; j < 8; j++) acc[i][j] = fmaf(a[i], b[j], acc[i][j]);
        }
        if (has_next) {
            const int nb = buf ^ 1;
            As[nb][ac + 0][ar] = av_n.x; As[nb][ac + 1][ar] = av_n.y;
            As[nb][ac + 2][ar] = av_n.z; As[nb][ac + 3][ar] = av_n.w;
            if (BT) {
                Bs[nb][ac + 0][ar] = bv_n.x; Bs[nb][ac + 1][ar] = bv_n.y;
                Bs[nb][ac + 2][ar] = bv_n.z; Bs[nb][ac + 3][ar] = bv_n.w;
            } else {
                *reinterpret_cast<float4*>(&Bs[nb][br][bc]) = bv_n;
            }
        }
        __syncthreads();
        buf ^= 1;
    }
#pragma unroll
    for (int i = 0; i < 8; i++) {
        int row = m0 + ty * 8 + i;
#pragma unroll
        for (int j = 0; j < 8; j++) {
            int col = n0 + tx * 8 + j;
            C[(size_t)row * ldc + col] = epi(acc[i][j], row, col);
        }
    }
}

// ---------------- epilogues --------------------------------------------------
struct EpiNone {
    __device__ float operator()(float a, int, int) const { return a; }
};
struct EpiBias {
    const float* b;
    __device__ float operator()(float a, int, int c) const { return a + b[c]; }
};
struct EpiBiasRes {
    const float* b; const float* r; int ldr;
    __device__ float operator()(float a, int row, int c) const {
        return a + b[c] + r[(size_t)row * ldr + c];
    }
};
struct EpiBiasGelu {
    const float* b;
    __device__ float operator()(float a, int, int c) const {
        float x = a + b[c];
        return 0.5f * x * (1.f + erff(x * 0.70710678118654752f));
    }
};
struct EpiScore {
    const float* mask;  // per-batch slice, length S
    __device__ float operator()(float a, int, int c) const {
        return a * ATTN_SCALE + mask[c];
    }
};

// ---------------- kernels ----------------------------------------------------
__global__ __launch_bounds__(256) void ln1_kernel(const float* __restrict__ x,
                                                  const float* __restrict__ g,
                                                  const float* __restrict__ b) {
    layernorm_row(x, g, b, g_h);
}
__global__ __launch_bounds__(256) void ln2_kernel(const float* __restrict__ g,
                                                  const float* __restrict__ b) {
    layernorm_row(g_x1, g, b, g_h);
}

__global__ __launch_bounds__(256) void qkv_kernel(const float* __restrict__ w,
                                                  const float* __restrict__ bias) {
    gemm_tile<false>(g_h, w, g_qkv, HH, HH, QLD, QLD, EpiBias{bias});
}

__global__ __launch_bounds__(256) void scores_kernel(const float* __restrict__ mask) {
    const int z = blockIdx.z, b = z / NHH, h = z % NHH;
    const float* Aq = g_qkv + (size_t)b * SS * QLD + h * DHH;          // Q
    const float* Bk = g_qkv + (size_t)b * SS * QLD + HH + h * DHH;     // K
    float* C = g_scores + (size_t)z * SS * SS;
    gemm_tile<true>(Aq, Bk, C, DHH, QLD, QLD, SS, EpiScore{mask + (size_t)b * SS});
}

__global__ __launch_bounds__(256) void softmax_kernel() {
    const size_t row = blockIdx.x;
    float* p = g_scores + row * (size_t)SS;
    const int tid = threadIdx.x;
    float v[8];
    float mx = -1e30f;
#pragma unroll
    for (int i = 0; i < 8; i++) { v[i] = p[tid + i * 256]; mx = fmaxf(mx, v[i]); }
    __shared__ float sh[8];
    __shared__ float s_b;
    float wm = warpReduceMax(mx);
    if ((tid & 31) == 0) sh[tid >> 5] = wm;
    __syncthreads();
    if (tid == 0) {
        float t = sh[0];
#pragma unroll
        for (int i = 1; i < 8; i++) t = fmaxf(t, sh[i]);
        s_b = t;
    }
    __syncthreads();
    const float m = s_b;
    float s = 0.f;
#pragma unroll
    for (int i = 0; i < 8; i++) { v[i] = expf(v[i] - m); s += v[i]; }
    float ws = warpReduceSum(s);
    if ((tid & 31) == 0) sh[tid >> 5] = ws;
    __syncthreads();
    if (tid == 0) {
        float t = 0.f;
#pragma unroll
        for (int i = 0; i < 8; i++) t += sh[i];
        s_b = 1.0f / t;
    }
    __syncthreads();
    const float inv = s_b;
#pragma unroll
    for (int i = 0; i < 8; i++) p[tid + i * 256] = v[i] * inv;
}

__global__ __launch_bounds__(256) void ctx_kernel() {
    const int z = blockIdx.z, b = z / NHH, h = z % NHH;
    const float* Ap = g_scores + (size_t)z * SS * SS;                   // probs
    const float* Bv = g_qkv + (size_t)b * SS * QLD + 2 * HH + h * DHH;  // V
    float* C = g_ctx + (size_t)b * SS * HH + h * DHH;
    gemm_tile<false>(Ap, Bv, C, SS, SS, QLD, HH, EpiNone{});
}

__global__ __launch_bounds__(256) void oproj_kernel(const float* __restrict__ w,
                                                    const float* __restrict__ bias,
                                                    const float* __restrict__ x) {
    gemm_tile<false>(g_ctx, w, g_x1, HH, HH, HH, HH, EpiBiasRes{bias, x, HH});
}

__global__ __launch_bounds__(256) void mlp1_kernel(const float* __restrict__ w,
                                                   const float* __restrict__ bias) {
    gemm_tile<false>(g_h, w, g_inter, HH, HH, FFF, FFF, EpiBiasGelu{bias});
}

__global__ __launch_bounds__(256) void mlp2_kernel(const float* __restrict__ w,
                                                   const float* __restrict__ bias,
                                                   float* __restrict__ out) {
    gemm_tile<false>(g_inter, w, out, FFF, FFF, HH, HH, EpiBiasRes{bias, g_x1, HH});
}

// ---------------- launch -----------------------------------------------------
extern "C" void kernel_launch(void* const* d_in, const int* in_sizes, int n_in,
                              void* d_out, int out_size) {
    const float* x     = (const float*)d_in[0];
    const float* mask  = (const float*)d_in[1];
    const float* ln1_g = (const float*)d_in[2];
    const float* ln1_b = (const float*)d_in[3];
    const float* w_qkv = (const float*)d_in[4];
    const float* b_qkv = (const float*)d_in[5];
    const float* w_o   = (const float*)d_in[6];
    const float* b_o   = (const float*)d_in[7];
    const float* ln2_g = (const float*)d_in[8];
    const float* ln2_b = (const float*)d_in[9];
    const float* w1    = (const float*)d_in[10];
    const float* b1    = (const float*)d_in[11];
    const float* w2    = (const float*)d_in[12];
    const float* b2    = (const float*)d_in[13];
    float* out = (float*)d_out;

    // h = LN1(x)
    ln1_kernel<<<MT, 256>>>(x, ln1_g, ln1_b);
    // qkv = h @ w_qkv + b_qkv
    qkv_kernel<<<dim3(QLD / 128, MT / 128), 256>>>(w_qkv, b_qkv);
    // scores = Q K^T * scale + mask
    scores_kernel<<<dim3(SS / 128, SS / 128, BB * NHH), 256>>>(mask);
    // softmax rows
    softmax_kernel<<<BB * NHH * SS, 256>>>();
    // ctx = P @ V
    ctx_kernel<<<dim3(1, SS / 128, BB * NHH), 256>>>();
    // x1 = x + ctx @ w_o + b_o
    oproj_kernel<<<dim3(HH / 128, MT / 128), 256>>>(w_o, b_o, x);
    // h = LN2(x1)
    ln2_kernel<<<MT, 256>>>(ln2_g, ln2_b);
    // inter = gelu(h @ w1 + b1)
    mlp1_kernel<<<dim3(FFF / 128, MT / 128), 256>>>(w1, b1);
    // out = x1 + inter @ w2 + b2
    mlp2_kernel<<<dim3(HH / 128, MT / 128), 256>>>(w2, b2, out);
}